// round 15
// baseline (speedup 1.0000x reference)
#include <cuda_runtime.h>
#include <cuda_fp16.h>
#include <cstdint>

// ============================================================================
// Problem constants
// ============================================================================
#define IN_DIM   4096
#define OUT_DIM  4096
#define MROWS    8192        // BSZ * SEQ
#define TRANK    64
#define LORA_SCALE 2.0f      // alpha/r = 32/16 for every adapter

// GEMM tiling: CTA 128x128, 4 warps, warp tile 64x64, 2 CTAs/SM, 6 stages.
#define BM 128
#define BN 128
#define BK 32
#define KT (IN_DIM / BK)          // 128 k-tiles
#define STAGES 6
#define A_BYTES (BM * BK * 2)     // 8192
#define B_BYTES (BN * BK * 2)     // 8192
#define STAGE_BYTES (A_BYTES + B_BYTES)   // 16384
#define SMEM_TOTAL (STAGES * STAGE_BYTES) // 98304 (x2 CTAs = 192KB)

#define NUM_PID_M (MROWS / BM)    // 64
#define NUM_PID_N (OUT_DIM / BN)  // 32
#define GRPM 16

// fused prologue (R12 config — proven 67us)
#define WEFF_BLOCKS 2048          // 128(n) x 64(k) W_eff tiles
#define CVT_BLOCKS  4096
#define WROW 144

// ============================================================================
// Device scratch (allocation-free rule: __device__ globals)
// ============================================================================
__device__ __half d_Xh[(size_t)MROWS * IN_DIM];    // 64 MiB
__device__ __half d_Wh[(size_t)OUT_DIM * IN_DIM];  // 32 MiB

// ============================================================================
// PTX helpers
// ============================================================================
__device__ __forceinline__ uint32_t smem_u32(const void* p) {
    uint32_t a;
    asm("{ .reg .u64 t; cvta.to.shared.u64 t, %1; cvt.u32.u64 %0, t; }"
        : "=r"(a) : "l"(p));
    return a;
}

#define CP_ASYNC16(dst, src) \
    asm volatile("cp.async.cg.shared.global [%0], [%1], 16;" \
                 :: "r"(dst), "l"(src) : "memory")
#define CP_COMMIT() asm volatile("cp.async.commit_group;" ::: "memory")
#define CP_WAIT4()  asm volatile("cp.async.wait_group 4;" ::: "memory")

__device__ __forceinline__ void ldmatrix_x4(uint32_t& r0, uint32_t& r1,
                                            uint32_t& r2, uint32_t& r3,
                                            uint32_t addr) {
    asm volatile("ldmatrix.sync.aligned.m8n8.x4.shared.b16 {%0,%1,%2,%3}, [%4];"
                 : "=r"(r0), "=r"(r1), "=r"(r2), "=r"(r3) : "r"(addr));
}
__device__ __forceinline__ void ldmatrix_x4_trans(uint32_t& r0, uint32_t& r1,
                                                  uint32_t& r2, uint32_t& r3,
                                                  uint32_t addr) {
    asm volatile("ldmatrix.sync.aligned.m8n8.x4.trans.shared.b16 {%0,%1,%2,%3}, [%4];"
                 : "=r"(r0), "=r"(r1), "=r"(r2), "=r"(r3) : "r"(addr));
}
__device__ __forceinline__ void mma16816(float* c, const uint32_t* a,
                                         const uint32_t* b) {
    asm volatile(
        "mma.sync.aligned.m16n8k16.row.col.f32.f16.f16.f32 "
        "{%0,%1,%2,%3}, {%4,%5,%6,%7}, {%8,%9}, {%0,%1,%2,%3};"
        : "+f"(c[0]), "+f"(c[1]), "+f"(c[2]), "+f"(c[3])
        : "r"(a[0]), "r"(a[1]), "r"(a[2]), "r"(a[3]), "r"(b[0]), "r"(b[1]));
}

// Swizzle for 64-byte rows, 16B chunks: phys_chunk = chunk ^ ((row>>1)&3)
__device__ __forceinline__ uint32_t sw_off(int row, int chunk) {
    return (uint32_t)(row * 64 + ((chunk ^ ((row >> 1) & 3)) << 4));
}

// ============================================================================
// Fused prologue (128 threads/block)  [R12 verbatim — proven 67us]:
//   blocks [0, WEFF_BLOCKS):  W_eff = W + 2*B@A -> d_Wh fp16 via mma.sync
//   blocks [WEFF_BLOCKS, +CVT_BLOCKS): x fp32 -> d_Xh fp16
// ============================================================================
__global__ void __launch_bounds__(128) fused_prologue_kernel(
    const float4* __restrict__ x,
    const float* __restrict__ W,
    const float* __restrict__ A,    // [64, 4096] fp32
    const float* __restrict__ Bl) { // [4096, 64] fp32
    __shared__ __align__(16) char psm[128 * WROW + 64 * WROW];
    const int tid = threadIdx.x;

    if (blockIdx.x < WEFF_BLOCKS) {
        const int nb = blockIdx.x >> 6;
        const int kb = blockIdx.x & 63;
        const int n0 = nb * 128;
        const int k0 = kb * 64;

        __half* sB = reinterpret_cast<__half*>(psm);
        __half* sA = reinterpret_cast<__half*>(psm + 128 * WROW);
        const uint32_t sb_u = smem_u32(sB);
        const uint32_t sa_u = smem_u32(sA);

        {
            const float4* src = reinterpret_cast<const float4*>(
                Bl + (size_t)(n0 + tid) * TRANK);
            char* dst = psm + tid * WROW;
#pragma unroll
            for (int c = 0; c < 16; c++) {
                float4 v = src[c];
                __half2 h0 = __floats2half2_rn(LORA_SCALE * v.x, LORA_SCALE * v.y);
                __half2 h1 = __floats2half2_rn(LORA_SCALE * v.z, LORA_SCALE * v.w);
                uint2 u;
                u.x = *reinterpret_cast<uint32_t*>(&h0);
                u.y = *reinterpret_cast<uint32_t*>(&h1);
                *reinterpret_cast<uint2*>(dst + c * 8) = u;
            }
        }
        {
            const int r = tid & 63;
            const int hsel = tid >> 6;
            const float4* src = reinterpret_cast<const float4*>(
                A + (size_t)r * IN_DIM + k0 + hsel * 32);
            char* dst = psm + 128 * WROW + r * WROW + hsel * 64;
#pragma unroll
            for (int c = 0; c < 8; c++) {
                float4 v = src[c];
                __half2 h0 = __floats2half2_rn(v.x, v.y);
                __half2 h1 = __floats2half2_rn(v.z, v.w);
                uint2 u;
                u.x = *reinterpret_cast<uint32_t*>(&h0);
                u.y = *reinterpret_cast<uint32_t*>(&h1);
                *reinterpret_cast<uint2*>(dst + c * 8) = u;
            }
        }
        __syncthreads();

        const int wid = tid >> 5, lane = tid & 31;
        const int ar = wid * 32 + (lane & 15);
        const int acg = lane >> 4;
        const int br = ((lane >> 3) & 1) * 8 + (lane & 7);
        const int bnoff = lane >> 4;

        float acc[2][8][4] = {};
#pragma unroll
        for (int kt = 0; kt < 4; kt++) {
            uint32_t af[2][4];
            uint32_t bf[8][2];
#pragma unroll
            for (int mt = 0; mt < 2; mt++) {
                const uint32_t addr = sb_u + (uint32_t)(ar + mt * 16) * WROW
                                    + kt * 32 + acg * 16;
                ldmatrix_x4(af[mt][0], af[mt][1], af[mt][2], af[mt][3], addr);
            }
#pragma unroll
            for (int nt = 0; nt < 8; nt += 2) {
                const uint32_t addr = sa_u + (uint32_t)(kt * 16 + br) * WROW
                                    + (nt + bnoff) * 16;
                ldmatrix_x4_trans(bf[nt][0], bf[nt][1],
                                  bf[nt + 1][0], bf[nt + 1][1], addr);
            }
#pragma unroll
            for (int mt = 0; mt < 2; mt++)
#pragma unroll
                for (int nt = 0; nt < 8; nt++)
                    mma16816(acc[mt][nt], af[mt], bf[nt]);
        }

        const int er = lane >> 2;
        const int ec = (lane & 3) * 2;
#pragma unroll
        for (int mt = 0; mt < 2; mt++) {
#pragma unroll
            for (int nt = 0; nt < 8; nt++) {
                const int r0 = n0 + wid * 32 + mt * 16 + er;
                const int c0 = k0 + nt * 8 + ec;
                float2 w0 = *reinterpret_cast<const float2*>(W + (size_t)r0 * IN_DIM + c0);
                float2 w1 = *reinterpret_cast<const float2*>(W + (size_t)(r0 + 8) * IN_DIM + c0);
                __half2 h0 = __floats2half2_rn(w0.x + acc[mt][nt][0],
                                               w0.y + acc[mt][nt][1]);
                __half2 h1 = __floats2half2_rn(w1.x + acc[mt][nt][2],
                                               w1.y + acc[mt][nt][3]);
                *reinterpret_cast<uint32_t*>(d_Wh + (size_t)r0 * IN_DIM + c0) =
                    *reinterpret_cast<uint32_t*>(&h0);
                *reinterpret_cast<uint32_t*>(d_Wh + (size_t)(r0 + 8) * IN_DIM + c0) =
                    *reinterpret_cast<uint32_t*>(&h1);
            }
        }
    } else {
        const int n8 = (MROWS * IN_DIM) / 8;
        const int stride = CVT_BLOCKS * 128;
        for (int i = (blockIdx.x - WEFF_BLOCKS) * 128 + tid; i < n8; i += stride) {
            float4 a = x[2 * i];
            float4 b = x[2 * i + 1];
            __half2 h0 = __floats2half2_rn(a.x, a.y);
            __half2 h1 = __floats2half2_rn(a.z, a.w);
            __half2 h2 = __floats2half2_rn(b.x, b.y);
            __half2 h3 = __floats2half2_rn(b.z, b.w);
            uint4 v;
            v.x = *reinterpret_cast<uint32_t*>(&h0);
            v.y = *reinterpret_cast<uint32_t*>(&h1);
            v.z = *reinterpret_cast<uint32_t*>(&h2);
            v.w = *reinterpret_cast<uint32_t*>(&h3);
            reinterpret_cast<uint4*>(d_Xh)[i] = v;
        }
    }
}

// ============================================================================
// Main GEMM: out[8192,4096] = Xh @ Whᵀ  (fp16 in, fp32 accum, mma.sync)
// CTA 128x128, 4 warps (2m x 2n), warp tile 64x64, 6-stage pipeline.
// NEW: all 16 LDSMs of a k-tile issued up front (double-buffered frags),
// then all 64 HMMAs — hides LDS latency of the 2nd ks-half behind MMAs.
// ============================================================================
__global__ void __launch_bounds__(128, 2) lora_gemm_kernel(float* __restrict__ out) {
    extern __shared__ __align__(1024) char smem[];
    const uint32_t sb = smem_u32(smem);
    const int tid = threadIdx.x;
    const int wid = tid >> 5, lane = tid & 31;
    const int warp_m = wid & 1;
    const int warp_n = wid >> 1;

    const int pid = blockIdx.x;
    const int group_size = GRPM * NUM_PID_N;
    const int group_id = pid / group_size;
    const int pid_in = pid - group_id * group_size;
    const int pid_m = group_id * GRPM + (pid_in % GRPM);
    const int pid_n = pid_in / GRPM;

    const int mbase = pid_m * BM;
    const int nbase = pid_n * BN;

    const __half* gX = d_Xh;
    const __half* gW = d_Wh;

    const int ld_row = tid >> 2;
    const int ld_c   = tid & 3;

    auto issue_stage = [&](int kt, int s) {
        const uint32_t base = sb + s * STAGE_BYTES;
        const size_t gk = (size_t)kt * BK + ld_c * 8;
#pragma unroll
        for (int p = 0; p < 4; p++) {
            const int row = ld_row + p * 32;
            const uint32_t off = sw_off(row, ld_c);
            CP_ASYNC16(base + off,
                       gX + (size_t)(mbase + row) * IN_DIM + gk);
            CP_ASYNC16(base + A_BYTES + off,
                       gW + (size_t)(nbase + row) * IN_DIM + gk);
        }
    };

#pragma unroll
    for (int i = 0; i < STAGES - 1; i++) {
        issue_stage(i, i);
        CP_COMMIT();
    }

    const int a_row_l = warp_m * 64 + (lane & 15);
    const int a_cgrp  = lane >> 4;
    const int b_row_l = warp_n * 64 + (lane & 7) + (((lane >> 4) & 1) << 3);
    const int b_cgrp  = (lane >> 3) & 1;

    float acc[4][8][4] = {};

    int s = 0;
    for (int kt = 0; kt < KT; kt++) {
        CP_WAIT4();
        __syncthreads();

        const int ktn = kt + STAGES - 1;
        if (ktn < KT) {
            int sn = s + STAGES - 1;
            if (sn >= STAGES) sn -= STAGES;
            issue_stage(ktn, sn);
        }
        CP_COMMIT();

        const uint32_t abase = sb + s * STAGE_BYTES;
        const uint32_t bbase = abase + A_BYTES;

        // ---- issue ALL fragment loads for both ks halves up front ----
        uint32_t af[2][4][4];
        uint32_t bf[2][8][2];
#pragma unroll
        for (int ks = 0; ks < 2; ks++) {
#pragma unroll
            for (int mt = 0; mt < 4; mt++) {
                const int row = a_row_l + mt * 16;
                ldmatrix_x4(af[ks][mt][0], af[ks][mt][1],
                            af[ks][mt][2], af[ks][mt][3],
                            abase + sw_off(row, ks * 2 + a_cgrp));
            }
#pragma unroll
            for (int np = 0; np < 4; np++) {
                const int row = b_row_l + np * 16;
                ldmatrix_x4(bf[ks][2 * np][0], bf[ks][2 * np][1],
                            bf[ks][2 * np + 1][0], bf[ks][2 * np + 1][1],
                            bbase + sw_off(row, ks * 2 + b_cgrp));
            }
        }
        // ---- then all 64 HMMAs ----
#pragma unroll
        for (int ks = 0; ks < 2; ks++)
#pragma unroll
            for (int mt = 0; mt < 4; mt++)
#pragma unroll
                for (int nt = 0; nt < 8; nt++)
                    mma16816(acc[mt][nt], af[ks][mt], bf[ks][nt]);

        if (++s == STAGES) s = 0;
    }

    const int er = lane >> 2;
    const int ec = (lane & 3) * 2;
#pragma unroll
    for (int mt = 0; mt < 4; mt++) {
#pragma unroll
        for (int nt = 0; nt < 8; nt++) {
            const int r0 = mbase + warp_m * 64 + mt * 16 + er;
            const int c0 = nbase + warp_n * 64 + nt * 8 + ec;
            float2 v0 = make_float2(acc[mt][nt][0], acc[mt][nt][1]);
            float2 v1 = make_float2(acc[mt][nt][2], acc[mt][nt][3]);
            *reinterpret_cast<float2*>(out + (size_t)r0 * OUT_DIM + c0) = v0;
            *reinterpret_cast<float2*>(out + (size_t)(r0 + 8) * OUT_DIM + c0) = v1;
        }
    }
}

// ============================================================================
// Host side
// ============================================================================
extern "C" void kernel_launch(void* const* d_in, const int* in_sizes, int n_in,
                              void* d_out, int out_size) {
    (void)in_sizes; (void)n_in; (void)out_size;
    const float* x  = (const float*)d_in[0];
    const float* w  = (const float*)d_in[1];
    const float* la = (const float*)d_in[2];
    const float* lb = (const float*)d_in[3];
    float* out = (float*)d_out;

    fused_prologue_kernel<<<WEFF_BLOCKS + CVT_BLOCKS, 128>>>(
        reinterpret_cast<const float4*>(x), w, la, lb);

    cudaFuncSetAttribute(lora_gemm_kernel,
                         cudaFuncAttributeMaxDynamicSharedMemorySize, SMEM_TOTAL);
    lora_gemm_kernel<<<NUM_PID_M * NUM_PID_N, 128, SMEM_TOTAL>>>(out);
}

// round 16
// speedup vs baseline: 1.5815x; 1.5815x over previous
#include <cuda_runtime.h>
#include <cuda_fp16.h>
#include <cstdint>

// ============================================================================
// Problem constants
// ============================================================================
#define IN_DIM   4096
#define OUT_DIM  4096
#define MROWS    8192        // BSZ * SEQ
#define TRANK    64
#define LORA_SCALE 2.0f      // alpha/r = 32/16 for every adapter

// GEMM tiling: CTA 128x128, 4 warps, warp tile 64x64, 2 CTAs/SM, 6 stages.
// [R12 verbatim — 552.6us, thrice-measured. DO NOT TOUCH]
#define BM 128
#define BN 128
#define BK 32
#define KT (IN_DIM / BK)          // 128 k-tiles
#define STAGES 6
#define A_BYTES (BM * BK * 2)     // 8192
#define B_BYTES (BN * BK * 2)     // 8192
#define STAGE_BYTES (A_BYTES + B_BYTES)   // 16384
#define SMEM_TOTAL (STAGES * STAGE_BYTES) // 98304 (x2 CTAs = 192KB)

#define NUM_PID_M (MROWS / BM)    // 64
#define NUM_PID_N (OUT_DIM / BN)  // 32
#define GRPM 16

// fused prologue
#define WEFF_BLOCKS 2048          // 128(n) x 64(k) W_eff tiles
#define CVT_BLOCKS  4096
#define WROW 144

// ============================================================================
// Device scratch (allocation-free rule: __device__ globals)
// ============================================================================
__device__ __half d_Xh[(size_t)MROWS * IN_DIM];    // 64 MiB
__device__ __half d_Wh[(size_t)OUT_DIM * IN_DIM];  // 32 MiB

// ============================================================================
// PTX helpers
// ============================================================================
__device__ __forceinline__ uint32_t smem_u32(const void* p) {
    uint32_t a;
    asm("{ .reg .u64 t; cvta.to.shared.u64 t, %1; cvt.u32.u64 %0, t; }"
        : "=r"(a) : "l"(p));
    return a;
}

#define CP_ASYNC16(dst, src) \
    asm volatile("cp.async.cg.shared.global [%0], [%1], 16;" \
                 :: "r"(dst), "l"(src) : "memory")
#define CP_COMMIT() asm volatile("cp.async.commit_group;" ::: "memory")
#define CP_WAIT4()  asm volatile("cp.async.wait_group 4;" ::: "memory")

__device__ __forceinline__ void ldmatrix_x4(uint32_t& r0, uint32_t& r1,
                                            uint32_t& r2, uint32_t& r3,
                                            uint32_t addr) {
    asm volatile("ldmatrix.sync.aligned.m8n8.x4.shared.b16 {%0,%1,%2,%3}, [%4];"
                 : "=r"(r0), "=r"(r1), "=r"(r2), "=r"(r3) : "r"(addr));
}
__device__ __forceinline__ void ldmatrix_x4_trans(uint32_t& r0, uint32_t& r1,
                                                  uint32_t& r2, uint32_t& r3,
                                                  uint32_t addr) {
    asm volatile("ldmatrix.sync.aligned.m8n8.x4.trans.shared.b16 {%0,%1,%2,%3}, [%4];"
                 : "=r"(r0), "=r"(r1), "=r"(r2), "=r"(r3) : "r"(addr));
}
__device__ __forceinline__ void mma16816(float* c, const uint32_t* a,
                                         const uint32_t* b) {
    asm volatile(
        "mma.sync.aligned.m16n8k16.row.col.f32.f16.f16.f32 "
        "{%0,%1,%2,%3}, {%4,%5,%6,%7}, {%8,%9}, {%0,%1,%2,%3};"
        : "+f"(c[0]), "+f"(c[1]), "+f"(c[2]), "+f"(c[3])
        : "r"(a[0]), "r"(a[1]), "r"(a[2]), "r"(a[3]), "r"(b[0]), "r"(b[1]));
}

// Swizzle for 64-byte rows, 16B chunks: phys_chunk = chunk ^ ((row>>1)&3)
__device__ __forceinline__ uint32_t sw_off(int row, int chunk) {
    return (uint32_t)(row * 64 + ((chunk ^ ((row >> 1) & 3)) << 4));
}

// ============================================================================
// Fused prologue (128 threads/block):
//   blocks [0, WEFF_BLOCKS):  W_eff = W + 2*B@A -> d_Wh fp16 via mma.sync
//     NEW: A/B staging loads COALESCED (consecutive lanes read consecutive
//     float4 within a row), then scattered to smem. Was 32-way replay.
//   blocks [WEFF_BLOCKS, +CVT_BLOCKS): x fp32 -> d_Xh fp16
// ============================================================================
__global__ void __launch_bounds__(128) fused_prologue_kernel(
    const float4* __restrict__ x,
    const float* __restrict__ W,
    const float* __restrict__ A,    // [64, 4096] fp32
    const float* __restrict__ Bl) { // [4096, 64] fp32
    __shared__ __align__(16) char psm[128 * WROW + 64 * WROW];
    const int tid = threadIdx.x;

    if (blockIdx.x < WEFF_BLOCKS) {
        const int nb = blockIdx.x >> 6;
        const int kb = blockIdx.x & 63;
        const int n0 = nb * 128;
        const int k0 = kb * 64;

        const uint32_t sb_u = smem_u32(psm);              // B lora fp16 [128][WROW]
        const uint32_t sa_u = sb_u + 128 * WROW;          // A lora fp16 [64][WROW]

        // ---- B staging: 128 rows x 64 fp32 (contiguous rows of 256B) ----
        // 2048 float4 chunks; consecutive tid -> consecutive chunk: coalesced.
        {
            const float4* srcB = reinterpret_cast<const float4*>(Bl) + (size_t)n0 * 16;
#pragma unroll
            for (int it = 0; it < 16; it++) {
                const int idx = it * 128 + tid;
                const int row = idx >> 4;
                const int c4  = idx & 15;         // float4 index within row
                float4 v = srcB[idx];
                __half2 h0 = __floats2half2_rn(LORA_SCALE * v.x, LORA_SCALE * v.y);
                __half2 h1 = __floats2half2_rn(LORA_SCALE * v.z, LORA_SCALE * v.w);
                uint2 u;
                u.x = *reinterpret_cast<uint32_t*>(&h0);
                u.y = *reinterpret_cast<uint32_t*>(&h1);
                *reinterpret_cast<uint2*>(psm + row * WROW + c4 * 8) = u;
            }
        }
        // ---- A staging: 64 rows x 64 fp32 (row segments of 256B) ----
        // 1024 chunks; warp = 2 rows x 256B contiguous segments: coalesced.
        {
#pragma unroll
            for (int it = 0; it < 8; it++) {
                const int idx = it * 128 + tid;
                const int row = idx >> 4;
                const int c4  = idx & 15;
                float4 v = reinterpret_cast<const float4*>(
                    A + (size_t)row * IN_DIM + k0)[c4];
                __half2 h0 = __floats2half2_rn(v.x, v.y);
                __half2 h1 = __floats2half2_rn(v.z, v.w);
                uint2 u;
                u.x = *reinterpret_cast<uint32_t*>(&h0);
                u.y = *reinterpret_cast<uint32_t*>(&h1);
                *reinterpret_cast<uint2*>(psm + 128 * WROW + row * WROW + c4 * 8) = u;
            }
        }
        __syncthreads();

        // ---- MMA: D[128n x 64k] = Bs[128 x 64rank] @ As[64rank x 64k] ----
        const int wid = tid >> 5, lane = tid & 31;
        const int ar = wid * 32 + (lane & 15);
        const int acg = lane >> 4;
        const int br = ((lane >> 3) & 1) * 8 + (lane & 7);
        const int bnoff = lane >> 4;

        float acc[2][8][4] = {};
#pragma unroll
        for (int kt = 0; kt < 4; kt++) {
            uint32_t af[2][4];
            uint32_t bf[8][2];
#pragma unroll
            for (int mt = 0; mt < 2; mt++) {
                const uint32_t addr = sb_u + (uint32_t)(ar + mt * 16) * WROW
                                    + kt * 32 + acg * 16;
                ldmatrix_x4(af[mt][0], af[mt][1], af[mt][2], af[mt][3], addr);
            }
#pragma unroll
            for (int nt = 0; nt < 8; nt += 2) {
                const uint32_t addr = sa_u + (uint32_t)(kt * 16 + br) * WROW
                                    + (nt + bnoff) * 16;
                ldmatrix_x4_trans(bf[nt][0], bf[nt][1],
                                  bf[nt + 1][0], bf[nt + 1][1], addr);
            }
#pragma unroll
            for (int mt = 0; mt < 2; mt++)
#pragma unroll
                for (int nt = 0; nt < 8; nt++)
                    mma16816(acc[mt][nt], af[mt], bf[nt]);
        }

        // ---- epilogue: W (sector-coalesced LDG.64) + acc -> fp16 d_Wh ----
        const int er = lane >> 2;
        const int ec = (lane & 3) * 2;
#pragma unroll
        for (int mt = 0; mt < 2; mt++) {
#pragma unroll
            for (int nt = 0; nt < 8; nt++) {
                const int r0 = n0 + wid * 32 + mt * 16 + er;
                const int c0 = k0 + nt * 8 + ec;
                float2 w0 = *reinterpret_cast<const float2*>(W + (size_t)r0 * IN_DIM + c0);
                float2 w1 = *reinterpret_cast<const float2*>(W + (size_t)(r0 + 8) * IN_DIM + c0);
                __half2 h0 = __floats2half2_rn(w0.x + acc[mt][nt][0],
                                               w0.y + acc[mt][nt][1]);
                __half2 h1 = __floats2half2_rn(w1.x + acc[mt][nt][2],
                                               w1.y + acc[mt][nt][3]);
                *reinterpret_cast<uint32_t*>(d_Wh + (size_t)r0 * IN_DIM + c0) =
                    *reinterpret_cast<uint32_t*>(&h0);
                *reinterpret_cast<uint32_t*>(d_Wh + (size_t)(r0 + 8) * IN_DIM + c0) =
                    *reinterpret_cast<uint32_t*>(&h1);
            }
        }
    } else {
        // ---- x fp32 -> fp16 ----
        const int n8 = (MROWS * IN_DIM) / 8;
        const int stride = CVT_BLOCKS * 128;
        for (int i = (blockIdx.x - WEFF_BLOCKS) * 128 + tid; i < n8; i += stride) {
            float4 a = x[2 * i];
            float4 b = x[2 * i + 1];
            __half2 h0 = __floats2half2_rn(a.x, a.y);
            __half2 h1 = __floats2half2_rn(a.z, a.w);
            __half2 h2 = __floats2half2_rn(b.x, b.y);
            __half2 h3 = __floats2half2_rn(b.z, b.w);
            uint4 v;
            v.x = *reinterpret_cast<uint32_t*>(&h0);
            v.y = *reinterpret_cast<uint32_t*>(&h1);
            v.z = *reinterpret_cast<uint32_t*>(&h2);
            v.w = *reinterpret_cast<uint32_t*>(&h3);
            reinterpret_cast<uint4*>(d_Xh)[i] = v;
        }
    }
}

// ============================================================================
// Main GEMM: out[8192,4096] = Xh @ Whᵀ  (fp16 in, fp32 accum, mma.sync)
// CTA 128x128, 4 warps (2m x 2n), warp tile 64x64, 6-stage pipeline,
// per-k-tile wait_group(4) + __syncthreads. 2 CTAs/SM.  [R12 verbatim]
// ============================================================================
__global__ void __launch_bounds__(128, 2) lora_gemm_kernel(float* __restrict__ out) {
    extern __shared__ __align__(1024) char smem[];
    const uint32_t sb = smem_u32(smem);
    const int tid = threadIdx.x;
    const int wid = tid >> 5, lane = tid & 31;
    const int warp_m = wid & 1;
    const int warp_n = wid >> 1;

    const int pid = blockIdx.x;
    const int group_size = GRPM * NUM_PID_N;
    const int group_id = pid / group_size;
    const int pid_in = pid - group_id * group_size;
    const int pid_m = group_id * GRPM + (pid_in % GRPM);
    const int pid_n = pid_in / GRPM;

    const int mbase = pid_m * BM;
    const int nbase = pid_n * BN;

    const __half* gX = d_Xh;
    const __half* gW = d_Wh;

    const int ld_row = tid >> 2;
    const int ld_c   = tid & 3;

    auto issue_stage = [&](int kt, int s) {
        const uint32_t base = sb + s * STAGE_BYTES;
        const size_t gk = (size_t)kt * BK + ld_c * 8;
#pragma unroll
        for (int p = 0; p < 4; p++) {
            const int row = ld_row + p * 32;
            const uint32_t off = sw_off(row, ld_c);
            CP_ASYNC16(base + off,
                       gX + (size_t)(mbase + row) * IN_DIM + gk);
            CP_ASYNC16(base + A_BYTES + off,
                       gW + (size_t)(nbase + row) * IN_DIM + gk);
        }
    };

#pragma unroll
    for (int i = 0; i < STAGES - 1; i++) {
        issue_stage(i, i);
        CP_COMMIT();
    }

    const int a_row_l = warp_m * 64 + (lane & 15);
    const int a_cgrp  = lane >> 4;
    const int b_row_l = warp_n * 64 + (lane & 7) + (((lane >> 4) & 1) << 3);
    const int b_cgrp  = (lane >> 3) & 1;

    float acc[4][8][4] = {};

    int s = 0;
    for (int kt = 0; kt < KT; kt++) {
        CP_WAIT4();
        __syncthreads();

        const int ktn = kt + STAGES - 1;
        if (ktn < KT) {
            int sn = s + STAGES - 1;
            if (sn >= STAGES) sn -= STAGES;
            issue_stage(ktn, sn);
        }
        CP_COMMIT();

        const uint32_t abase = sb + s * STAGE_BYTES;
        const uint32_t bbase = abase + A_BYTES;

#pragma unroll
        for (int ks = 0; ks < 2; ks++) {
            uint32_t af[4][4];
            uint32_t bf[8][2];
#pragma unroll
            for (int mt = 0; mt < 4; mt++) {
                const int row = a_row_l + mt * 16;
                ldmatrix_x4(af[mt][0], af[mt][1], af[mt][2], af[mt][3],
                            abase + sw_off(row, ks * 2 + a_cgrp));
            }
#pragma unroll
            for (int np = 0; np < 4; np++) {
                const int row = b_row_l + np * 16;
                ldmatrix_x4(bf[2 * np][0], bf[2 * np][1],
                            bf[2 * np + 1][0], bf[2 * np + 1][1],
                            bbase + sw_off(row, ks * 2 + b_cgrp));
            }
#pragma unroll
            for (int mt = 0; mt < 4; mt++)
#pragma unroll
                for (int nt = 0; nt < 8; nt++)
                    mma16816(acc[mt][nt], af[mt], bf[nt]);
        }

        if (++s == STAGES) s = 0;
    }

    const int er = lane >> 2;
    const int ec = (lane & 3) * 2;
#pragma unroll
    for (int mt = 0; mt < 4; mt++) {
#pragma unroll
        for (int nt = 0; nt < 8; nt++) {
            const int r0 = mbase + warp_m * 64 + mt * 16 + er;
            const int c0 = nbase + warp_n * 64 + nt * 8 + ec;
            float2 v0 = make_float2(acc[mt][nt][0], acc[mt][nt][1]);
            float2 v1 = make_float2(acc[mt][nt][2], acc[mt][nt][3]);
            *reinterpret_cast<float2*>(out + (size_t)r0 * OUT_DIM + c0) = v0;
            *reinterpret_cast<float2*>(out + (size_t)(r0 + 8) * OUT_DIM + c0) = v1;
        }
    }
}

// ============================================================================
// Host side
// ============================================================================
extern "C" void kernel_launch(void* const* d_in, const int* in_sizes, int n_in,
                              void* d_out, int out_size) {
    (void)in_sizes; (void)n_in; (void)out_size;
    const float* x  = (const float*)d_in[0];
    const float* w  = (const float*)d_in[1];
    const float* la = (const float*)d_in[2];
    const float* lb = (const float*)d_in[3];
    float* out = (float*)d_out;

    fused_prologue_kernel<<<WEFF_BLOCKS + CVT_BLOCKS, 128>>>(
        reinterpret_cast<const float4*>(x), w, la, lb);

    cudaFuncSetAttribute(lora_gemm_kernel,
                         cudaFuncAttributeMaxDynamicSharedMemorySize, SMEM_TOTAL);
    lora_gemm_kernel<<<NUM_PID_M * NUM_PID_N, 128, SMEM_TOTAL>>>(out);
}